// round 14
// baseline (speedup 1.0000x reference)
#include <cuda_runtime.h>
#include <cuda_fp16.h>
#include <cstdint>

// Persistent single-kernel MLP: x[N,16] -> L1+BN+ReLU -> L2+BN+ReLU -> L3+BN+ReLU -> L4(->1)
// v9 = v8 (fp16 z storage, cp.async double-buffer, store-phase stats) with the GEMM
// remapped to 8 feats x 4 rows per thread, feature-quarter in the LOW lane bits so the
// 4 readers of each row chunk form a quad -> LDS same-address broadcast (1 wf/act load),
// and weight-broadcast LDS amortized over 4 rows (64 instr/thread, was 128).

#define EPSV 1e-5f
#define NCTA 296
#define TR 256                  // tile rows
#define TBUF_U 4352             // uints per buffer: max(staging 4096u, scratch 256*17=4352u)

__device__ uint4 g_Z16[(size_t)2097152 * 4];       // z as half2: 4 uint4 (32 halfs) per row
__device__ float g_partial[NCTA * 64];
__device__ float g_bnab[64];                       // a[32], c[32]
__device__ unsigned int g_cnt[4]  = {0, 0, 0, 0};  // monotonic across graph replays
__device__ unsigned int g_flag[4] = {0, 0, 0, 0};

// ---------------- packed f32x2 helpers ----------------
__device__ __forceinline__ unsigned long long pack2(float lo, float hi) {
    unsigned long long r;
    asm("mov.b64 %0, {%1, %2};" : "=l"(r) : "r"(__float_as_uint(lo)), "r"(__float_as_uint(hi)));
    return r;
}
__device__ __forceinline__ void unpack2(unsigned long long v, float& lo, float& hi) {
    unsigned int a, b;
    asm("mov.b64 {%0, %1}, %2;" : "=r"(a), "=r"(b) : "l"(v));
    lo = __uint_as_float(a); hi = __uint_as_float(b);
}
__device__ __forceinline__ unsigned long long splat2(float x) {
    unsigned long long r;
    unsigned int xi = __float_as_uint(x);
    asm("mov.b64 %0, {%1, %1};" : "=l"(r) : "r"(xi));
    return r;
}
__device__ __forceinline__ void fma2(unsigned long long& d, unsigned long long a, unsigned long long b) {
    asm("fma.rn.f32x2 %0, %1, %2, %0;" : "+l"(d) : "l"(a), "l"(b));
}
__device__ __forceinline__ void add2(unsigned long long& d, unsigned long long a) {
    asm("add.rn.f32x2 %0, %0, %1;" : "+l"(d) : "l"(a));
}

// ---------------- fp16 pack/unpack ----------------
__device__ __forceinline__ unsigned int f22h2(float lo, float hi) {
    __half2 h = __floats2half2_rn(lo, hi);
    return *reinterpret_cast<unsigned int*>(&h);
}
__device__ __forceinline__ float2 h22f2(unsigned int u) {
    __half2 h = *reinterpret_cast<__half2*>(&u);
    return __half22float2(h);
}

// ---------------- async copy + sync helpers ----------------
__device__ __forceinline__ unsigned int smem_u32(const void* p) {
    return (unsigned int)__cvta_generic_to_shared(p);
}
__device__ __forceinline__ void cp16(unsigned int dst, const void* src) {
    asm volatile("cp.async.cg.shared.global [%0], [%1], 16;" :: "r"(dst), "l"(src));
}
__device__ __forceinline__ void cp_commit() { asm volatile("cp.async.commit_group;" ::: "memory"); }
__device__ __forceinline__ void cp_wait1()  { asm volatile("cp.async.wait_group 1;" ::: "memory"); }
__device__ __forceinline__ void cp_wait0()  { asm volatile("cp.async.wait_group 0;" ::: "memory"); }
__device__ __forceinline__ unsigned int ld_acq(unsigned int* p) {
    unsigned int v;
    asm volatile("ld.acquire.gpu.u32 %0, [%1];" : "=r"(v) : "l"(p));
    return v;
}
__device__ __forceinline__ void st_rel(unsigned int* p, unsigned int v) {
    asm volatile("st.release.gpu.u32 [%0], %1;" :: "l"(p), "r"(v));
}

struct __align__(16) Smem {
    unsigned int Tu[2][TBUF_U];          // staging (swizzled 16B chunks) / z scratch (stride-17 half2)
    unsigned long long Wp[32 * 16];      // Wp[k*16+jj] = {W[2jj][k], W[2jj+1][k]}
    unsigned long long Bp[16];
    __align__(16) float A[32];           // BN scale of input layer
    __align__(16) float C[32];           // BN shift
    float Stot[64];
    unsigned int ticket;
};

// 16B-chunk swizzles (4 chunks per row for both fp32-KIN16 and fp16-KIN32 tiles)
__device__ __forceinline__ int swzF(int row, int c) {  // fp32 x, 16 floats/row
    return row * 4 + ((c + (row >> 1)) & 3);
}
__device__ __forceinline__ int swzH(int row, int c) {  // fp16 z, 16 half2/row
    return row * 4 + (c ^ ((row >> 1) & 3));
}

// ---------------- one layer: z = BNReLU(zin) @ W^T + b  (z stored fp16), stats of z ----------------
template<int KIN, bool BN, bool HALF_IN>
__device__ void run_layer(Smem& sm, const void* __restrict__ zin,
                          const float* __restrict__ W, const float* __restrict__ b,
                          int ntiles, int tid)
{
    for (int idx = tid; idx < KIN * 16; idx += 256) {
        int k = idx >> 4, jj = idx & 15;
        sm.Wp[idx] = pack2(W[(2 * jj) * KIN + k], W[(2 * jj + 1) * KIN + k]);
    }
    if (tid < 16) sm.Bp[tid] = pack2(b[2 * tid], b[2 * tid + 1]);
    __syncthreads();

    const int q  = tid & 3;          // feature quarter: feats q*8 .. q*8+7 (LOW lane bits!)
    const int rs = tid >> 2;         // row slot 0..63; thread owns rows rs + 64p, p=0..3

    // store-phase stat accumulators: 8 fixed features (tid&3)*8 .. +7
    unsigned long long ss[4], qq[4];
#pragma unroll
    for (int m = 0; m < 4; ++m) { ss[m] = 0ull; qq[m] = 0ull; }

    // tiles are 1024 16B-chunks in gmem for both input types (256 rows x 64B)
    const uint4* gsrc = reinterpret_cast<const uint4*>(zin);

    // prologue: prefetch first tile into buffer 0
    const int t0 = blockIdx.x;
    {
        const uint4* src = gsrc + (size_t)t0 * 1024;
        unsigned int* dstT = sm.Tu[0];
#pragma unroll
        for (int j = 0; j < 4; ++j) {
            int i = tid + 256 * j;
            int row = i >> 2, c = i & 3;
            int sidx = HALF_IN ? swzH(row, c) : swzF(row, c);
            cp16(smem_u32(dstT + sidx * 4), src + i);
        }
        cp_commit();
    }

    int it = 0;
    for (int t = t0; t < ntiles; t += NCTA, ++it) {
        const int cur = it & 1;

        const int tn = t + NCTA;
        if (tn < ntiles) {
            const uint4* src = gsrc + (size_t)tn * 1024;
            unsigned int* dstT = sm.Tu[cur ^ 1];
#pragma unroll
            for (int j = 0; j < 4; ++j) {
                int i = tid + 256 * j;
                int row = i >> 2, c = i & 3;
                int sidx = HALF_IN ? swzH(row, c) : swzF(row, c);
                cp16(smem_u32(dstT + sidx * 4), src + i);
            }
        }
        cp_commit();
        cp_wait1();
        __syncthreads();

        unsigned int* T = sm.Tu[cur];

        // ---- GEMM: 8 features x 4 rows per thread ----
        unsigned long long zz[4][4];
#pragma unroll
        for (int p = 0; p < 4; ++p)
#pragma unroll
            for (int m = 0; m < 4; ++m) zz[p][m] = sm.Bp[q * 4 + m];

        if (HALF_IN) {
            const uint4* T4 = reinterpret_cast<const uint4*>(T);
#pragma unroll
            for (int c = 0; c < 4; ++c) {
                uint4 h[4];
#pragma unroll
                for (int p = 0; p < 4; ++p) h[p] = T4[swzH(rs + 64 * p, c)];
#pragma unroll
                for (int tq = 0; tq < 4; ++tq) {
                    float2 f[4];
#pragma unroll
                    for (int p = 0; p < 4; ++p)
                        f[p] = h22f2(reinterpret_cast<const unsigned int*>(&h[p])[tq]);
                    if (BN) {
                        float2 a2 = reinterpret_cast<const float2*>(sm.A)[c * 4 + tq];
                        float2 c2 = reinterpret_cast<const float2*>(sm.C)[c * 4 + tq];
#pragma unroll
                        for (int p = 0; p < 4; ++p) {
                            f[p].x = fmaxf(fmaf(f[p].x, a2.x, c2.x), 0.0f);
                            f[p].y = fmaxf(fmaf(f[p].y, a2.y, c2.y), 0.0f);
                        }
                    }
#pragma unroll
                    for (int e = 0; e < 2; ++e) {
                        int k = c * 8 + tq * 2 + e;
                        ulonglong2 w01 = *reinterpret_cast<const ulonglong2*>(&sm.Wp[k * 16 + q * 4]);
                        ulonglong2 w23 = *reinterpret_cast<const ulonglong2*>(&sm.Wp[k * 16 + q * 4 + 2]);
#pragma unroll
                        for (int p = 0; p < 4; ++p) {
                            unsigned long long pk = splat2(e ? f[p].y : f[p].x);
                            fma2(zz[p][0], pk, w01.x);
                            fma2(zz[p][1], pk, w01.y);
                            fma2(zz[p][2], pk, w23.x);
                            fma2(zz[p][3], pk, w23.y);
                        }
                    }
                }
            }
        } else {
            const float4* T4f = reinterpret_cast<const float4*>(T);
#pragma unroll
            for (int c = 0; c < 4; ++c) {
                float4 v[4];
#pragma unroll
                for (int p = 0; p < 4; ++p) v[p] = T4f[swzF(rs + 64 * p, c)];
#pragma unroll
                for (int u = 0; u < 4; ++u) {
                    int k = c * 4 + u;
                    ulonglong2 w01 = *reinterpret_cast<const ulonglong2*>(&sm.Wp[k * 16 + q * 4]);
                    ulonglong2 w23 = *reinterpret_cast<const ulonglong2*>(&sm.Wp[k * 16 + q * 4 + 2]);
#pragma unroll
                    for (int p = 0; p < 4; ++p) {
                        unsigned long long pk = splat2(reinterpret_cast<const float*>(&v[p])[u]);
                        fma2(zz[p][0], pk, w01.x);
                        fma2(zz[p][1], pk, w01.y);
                        fma2(zz[p][2], pk, w23.x);
                        fma2(zz[p][3], pk, w23.y);
                    }
                }
            }
        }
        __syncthreads();                 // all GEMM reads of T done

        // ---- scatter z as half2 into scratch (stride-17 uints) ----
#pragma unroll
        for (int p = 0; p < 4; ++p)
#pragma unroll
            for (int m = 0; m < 4; ++m) {
                float lo, hi;
                unpack2(zz[p][m], lo, hi);
                T[(rs + 64 * p) * 17 + q * 4 + m] = f22h2(lo, hi);
            }
        __syncthreads();

        // ---- coalesced fp16 z store + stat accumulation (features fixed per thread) ----
        uint4* dst = g_Z16 + (size_t)t * 1024;
#pragma unroll
        for (int j = 0; j < 4; ++j) {
            int i = tid + 256 * j;
            int row = i >> 2, qc = i & 3;                 // qc = tid & 3 (fixed)
            const unsigned int* s = &T[row * 17 + qc * 4];
            unsigned int w0 = s[0], w1 = s[1], w2 = s[2], w3 = s[3];
            uint4 v4; v4.x = w0; v4.y = w1; v4.z = w2; v4.w = w3;
            dst[i] = v4;
            const unsigned int ww[4] = {w0, w1, w2, w3};
#pragma unroll
            for (int m = 0; m < 4; ++m) {
                float2 f = h22f2(ww[m]);
                unsigned long long p = pack2(f.x, f.y);
                add2(ss[m], p);
                fma2(qq[m], p, p);
            }
        }
        __syncthreads();                 // scratch free before next prefetch cycle
    }
    cp_wait0();
    __syncthreads();

    // ---- deterministic stat reduction -> per-CTA partials ----
    // Thread owns features fb..fb+7 where fb = (tid&3)*8. Regroup through smem.
    {
        float* SS = reinterpret_cast<float*>(sm.Tu[0]);   // 4096 floats, staging dead
#pragma unroll
        for (int m = 0; m < 4; ++m) {
            float a0, a1;
            unpack2(ss[m], a0, a1);
            SS[tid * 16 + 2 * m]     = a0;
            SS[tid * 16 + 2 * m + 1] = a1;
            unpack2(qq[m], a0, a1);
            SS[tid * 16 + 8 + 2 * m]     = a0;
            SS[tid * 16 + 8 + 2 * m + 1] = a1;
        }
        __syncthreads();
        if (tid < 64) {
            const int f = tid & 31, s = tid >> 5;        // feature, stat (0=sum,1=sumsq)
            const int g = f >> 3, u = (f & 7) + s * 8;   // owner group (tid&3), slot
            float tot = 0.0f;
#pragma unroll
            for (int m = 0; m < 64; ++m) tot += SS[(g + 4 * m) * 16 + u];
            g_partial[blockIdx.x * 64 + tid] = tot;
        }
        __syncthreads();
    }
}

// ---------------- grid barrier + cross-CTA BN coefficient reduction ----------------
__device__ void bn_barrier(Smem& sm, int ph, const float* __restrict__ gamma,
                           const float* __restrict__ beta, float invN, int tid)
{
    __threadfence();
    __syncthreads();
    if (tid == 0) sm.ticket = atomicAdd(&g_cnt[ph], 1);
    __syncthreads();
    const unsigned int ticket = sm.ticket;
    const unsigned int need = ticket - (ticket % NCTA) + NCTA;

    if (ticket % NCTA == NCTA - 1) {
        __threadfence();
        if (tid < 64) {
            float s0 = 0.f, s1 = 0.f;
            for (int c = 0; c < NCTA - 1; c += 2) {
                s0 += g_partial[c * 64 + tid];
                s1 += g_partial[(c + 1) * 64 + tid];
            }
            sm.Stot[tid] = s0 + s1;
        }
        __syncthreads();
        if (tid < 32) {
            float mean = sm.Stot[tid] * invN;
            float var  = sm.Stot[32 + tid] * invN - mean * mean;
            float a = gamma[tid] * rsqrtf(var + EPSV);
            g_bnab[tid]      = a;
            g_bnab[32 + tid] = beta[tid] - mean * a;
        }
        __threadfence();
        __syncthreads();
        if (tid == 0) st_rel(&g_flag[ph], need);
    }
    if (tid == 0) {
        while ((int)(ld_acq(&g_flag[ph]) - need) < 0) __nanosleep(128);
    }
    __syncthreads();
    if (tid < 32) { sm.A[tid] = g_bnab[tid]; sm.C[tid] = g_bnab[32 + tid]; }
    __syncthreads();
}

// ---------------- the persistent kernel ----------------
__global__ void __launch_bounds__(256, 2) mlp_kernel(
    const float* __restrict__ x,
    const float* __restrict__ W1, const float* __restrict__ b1,
    const float* __restrict__ g1, const float* __restrict__ be1,
    const float* __restrict__ W2, const float* __restrict__ b2,
    const float* __restrict__ g2, const float* __restrict__ be2,
    const float* __restrict__ W3, const float* __restrict__ b3,
    const float* __restrict__ g3, const float* __restrict__ be3,
    const float* __restrict__ W4, const float* __restrict__ b4,
    float* __restrict__ out, int ntiles, int nrows, float invN)
{
    extern __shared__ char smem_raw[];
    Smem& sm = *reinterpret_cast<Smem*>(smem_raw);
    const int tid = threadIdx.x;

    run_layer<16, false, false>(sm, x, W1, b1, ntiles, tid);
    bn_barrier(sm, 0, g1, be1, invN, tid);

    run_layer<32, true, true>(sm, g_Z16, W2, b2, ntiles, tid);
    bn_barrier(sm, 1, g2, be2, invN, tid);

    run_layer<32, true, true>(sm, g_Z16, W3, b3, ntiles, tid);
    bn_barrier(sm, 2, g3, be3, invN, tid);

    // L4: BN3ReLU(z3) . w4 + b4
    if (tid < 32) sm.Stot[tid] = W4[tid];
    __syncthreads();
    const float bb = b4[0];
    for (size_t i = (size_t)blockIdx.x * 256 + tid; i < (size_t)nrows; i += (size_t)NCTA * 256) {
        const uint4* zr = g_Z16 + i * 4;
        float acc = bb;
#pragma unroll
        for (int q = 0; q < 4; ++q) {
            uint4 hv = zr[q];
            const unsigned int hu[4] = {hv.x, hv.y, hv.z, hv.w};
#pragma unroll
            for (int m = 0; m < 4; ++m) {
                int k = q * 8 + m * 2;
                float2 f = h22f2(hu[m]);
                acc = fmaf(fmaxf(fmaf(f.x, sm.A[k],     sm.C[k]),     0.0f), sm.Stot[k],     acc);
                acc = fmaf(fmaxf(fmaf(f.y, sm.A[k + 1], sm.C[k + 1]), 0.0f), sm.Stot[k + 1], acc);
            }
        }
        out[i] = acc;
    }
}

// ---------------- launcher ----------------
extern "C" void kernel_launch(void* const* d_in, const int* in_sizes, int n_in,
                              void* d_out, int out_size)
{
    const float* x   = (const float*)d_in[0];
    const float* W1  = (const float*)d_in[1];
    const float* b1  = (const float*)d_in[2];
    const float* g1  = (const float*)d_in[3];
    const float* be1 = (const float*)d_in[4];
    const float* W2  = (const float*)d_in[5];
    const float* b2  = (const float*)d_in[6];
    const float* g2  = (const float*)d_in[7];
    const float* be2 = (const float*)d_in[8];
    const float* W3  = (const float*)d_in[9];
    const float* b3  = (const float*)d_in[10];
    const float* g3  = (const float*)d_in[11];
    const float* be3 = (const float*)d_in[12];
    const float* W4  = (const float*)d_in[13];
    const float* b4  = (const float*)d_in[14];

    const int n      = in_sizes[0] / 16;        // 2097152 rows
    const int ntiles = n / TR;                  // 8192
    const float invN = 1.0f / (float)n;

    const int smem_bytes = (int)sizeof(Smem);
    cudaFuncSetAttribute(mlp_kernel, cudaFuncAttributeMaxDynamicSharedMemorySize, smem_bytes);

    mlp_kernel<<<NCTA, 256, smem_bytes>>>(x, W1, b1, g1, be1, W2, b2, g2, be2,
                                          W3, b3, g3, be3, W4, b4,
                                          (float*)d_out, ntiles, n, invN);
}